// round 8
// baseline (speedup 1.0000x reference)
#include <cuda_runtime.h>
#include <cuda_bf16.h>

#define N_NODES  50000
#define N_EDGESC 1600000
#define ET       1650000            // edges + self loops
#define F        128
#define FE       32
#define NG       512
#define NC       10
#define SLOPE    0.2f

typedef unsigned long long u64;

// ---------------- f32x2 helpers (Blackwell packed fp32) ----------------------
__device__ __forceinline__ u64 pack2(float x, float y) {
    u64 r; asm("mov.b64 %0, {%1, %2};" : "=l"(r) : "f"(x), "f"(y)); return r;
}
__device__ __forceinline__ float2 unpack2(u64 v) {
    float2 f; asm("mov.b64 {%0, %1}, %2;" : "=f"(f.x), "=f"(f.y) : "l"(v)); return f;
}
__device__ __forceinline__ u64 ffma2(u64 a, u64 b, u64 c) {
    u64 d; asm("fma.rn.f32x2 %0, %1, %2, %3;" : "=l"(d) : "l"(a), "l"(b), "l"(c)); return d;
}

// ---------------- scratch (device globals: allocation-free rule) -------------
__device__ float g_eas[(size_t)ET * FE];   // edge attrs permuted into CSR order (211MB)
__device__ float g_score[ET];
__device__ float g_xl[(size_t)N_NODES * F];
__device__ float g_xr[(size_t)N_NODES * F];
__device__ float g_hA[(size_t)N_NODES * F];
__device__ float g_hB[(size_t)N_NODES * F];
__device__ int   g_deg[N_NODES];
__device__ int   g_rowptr[N_NODES + 1];
__device__ int   g_cnt[N_NODES];
__device__ int   g_srcs[ET];
__device__ int   g_eids[ET];
__device__ int   g_dsts[ET];
__device__ int   g_gptr[NG + 1];
__device__ float g_pool[NG * F];
__device__ int   g_is64;                   // 1 if index arrays are int64, 0 if int32

// ---------------- index dtype handling --------------------------------------
__global__ void k_probe(const void* __restrict__ ei) {
    const unsigned* w = (const unsigned*)ei;
    if (threadIdx.x == 0) {
        int all0 = 1;
        #pragma unroll
        for (int i = 0; i < 64; i++) all0 &= (w[2 * i + 1] == 0u);
        g_is64 = all0;
    }
}
__device__ __forceinline__ int getIdx(const void* __restrict__ p, long long i) {
    if (g_is64) return (int)((const long long*)p)[i];
    return ((const int*)p)[i];
}

// ---------------- preprocessing ---------------------------------------------
__global__ void k_zero() {
    int i = blockIdx.x * blockDim.x + threadIdx.x;
    if (i < N_NODES) { g_deg[i] = 0; g_cnt[i] = 0; }
}

__global__ void k_deg(const void* __restrict__ ei) {
    int e = blockIdx.x * blockDim.x + threadIdx.x;
    if (e >= N_EDGESC) return;
    atomicAdd(&g_deg[getIdx(ei, (long long)N_EDGESC + e)], 1);
}

// exclusive scan of (deg+1) -> rowptr; single block, warp-shfl based
__global__ void k_scan() {
    __shared__ int sw[32];
    __shared__ int sc;
    int tid = threadIdx.x, lane = tid & 31, wid = tid >> 5;
    if (tid == 0) sc = 0;
    __syncthreads();
    for (int base = 0; base < N_NODES; base += 1024) {
        int idx = base + tid;
        int orig = (idx < N_NODES) ? (g_deg[idx] + 1) : 0;
        int v = orig;
        #pragma unroll
        for (int off = 1; off < 32; off <<= 1) {
            int t = __shfl_up_sync(0xffffffffu, v, off);
            if (lane >= off) v += t;
        }
        if (lane == 31) sw[wid] = v;
        __syncthreads();
        if (wid == 0) {
            int w = sw[lane];
            #pragma unroll
            for (int off = 1; off < 32; off <<= 1) {
                int t = __shfl_up_sync(0xffffffffu, w, off);
                if (lane >= off) w += t;
            }
            sw[lane] = w;
        }
        __syncthreads();
        int c0 = sc;
        int incl = v + (wid ? sw[wid - 1] : 0);
        if (idx < N_NODES) g_rowptr[idx] = c0 + incl - orig;
        int tot = sw[31];
        __syncthreads();
        if (tid == 0) sc = c0 + tot;
        __syncthreads();
    }
    if (threadIdx.x == 0) g_rowptr[N_NODES] = sc;   // == ET
}

// place self-loops first in each CSR row
__global__ void k_self() {
    int v = blockIdx.x * blockDim.x + threadIdx.x;
    if (v >= N_NODES) return;
    int p = g_rowptr[v];
    g_srcs[p] = v;
    g_eids[p] = N_EDGESC + v;
    g_dsts[p] = v;
}

// counting-sort scatter of real edges by dst
__global__ void k_scatter(const void* __restrict__ ei) {
    int e = blockIdx.x * blockDim.x + threadIdx.x;
    if (e >= N_EDGESC) return;
    int src = getIdx(ei, e);
    int dst = getIdx(ei, (long long)N_EDGESC + e);
    int p = g_rowptr[dst] + 1 + atomicAdd(&g_cnt[dst], 1);
    g_srcs[p] = src;
    g_eids[p] = e;
    g_dsts[p] = dst;
}

// permute real-edge attrs into CSR slot order (coalesced writes)
__global__ void __launch_bounds__(256) k_permute(const float* __restrict__ ea) {
    int wid = (blockIdx.x * blockDim.x + threadIdx.x) >> 5;
    int nw  = (gridDim.x * blockDim.x) >> 5;
    int lane = threadIdx.x & 31;
    for (int i = wid; i < ET; i += nw) {
        int e = g_eids[i];
        if (e < N_EDGESC)
            g_eas[(long long)i * FE + lane] = ea[(long long)e * FE + lane];
    }
}

// self-loop attr = mean of incoming attrs; reads CSR-ordered attrs contiguously
__global__ void __launch_bounds__(256) k_loopcsr() {
    int wid = (blockIdx.x * blockDim.x + threadIdx.x) >> 5;
    if (wid >= N_NODES) return;
    int lane = threadIdx.x & 31;
    int beg = g_rowptr[wid], end = g_rowptr[wid + 1];
    float acc = 0.f;
    #pragma unroll 4
    for (int i = beg + 1; i < end; i++)
        acc += g_eas[(long long)i * FE + lane];
    float d = (float)(end - beg - 1);
    g_eas[(long long)beg * FE + lane] = acc / fmaxf(d, 1.f);
}

// ---------------- node GEMMs: xl = h@Wl + bl, xr = h@Wr + br ------------------
__global__ void __launch_bounds__(128) k_xlxr(
    const float* __restrict__ x_ext, int hin_sel,
    const float* __restrict__ Wl, const float* __restrict__ bl,
    const float* __restrict__ Wr, const float* __restrict__ br) {
    const float* h = (hin_sel == 0) ? x_ext : (hin_sel == 1 ? g_hA : g_hB);
    __shared__ float shT[F][34];
    int j = threadIdx.x;
    int r0 = blockIdx.x * 32;
    #pragma unroll
    for (int r = 0; r < 32; r++) {
        int row = r0 + r;
        shT[j][r] = (row < N_NODES) ? h[(long long)row * F + j] : 0.f;
    }
    __syncthreads();
    u64 aL[16], aR[16];
    {
        u64 bl2 = pack2(bl[j], bl[j]);
        u64 br2 = pack2(br[j], br[j]);
        #pragma unroll
        for (int rp = 0; rp < 16; rp++) { aL[rp] = bl2; aR[rp] = br2; }
    }
    #pragma unroll 2
    for (int k = 0; k < F; k++) {
        float wl = Wl[k * F + j];
        float wr = Wr[k * F + j];
        u64 wl2 = pack2(wl, wl);
        u64 wr2 = pack2(wr, wr);
        #pragma unroll
        for (int rp = 0; rp < 16; rp++) {
            u64 hv2 = *(const u64*)&shT[k][2 * rp];
            aL[rp] = ffma2(hv2, wl2, aL[rp]);
            aR[rp] = ffma2(hv2, wr2, aR[rp]);
        }
    }
    #pragma unroll
    for (int rp = 0; rp < 16; rp++) {
        float2 l = unpack2(aL[rp]);
        float2 r = unpack2(aR[rp]);
        int row = r0 + 2 * rp;
        if (row < N_NODES)     { g_xl[(long long)row * F + j] = l.x; g_xr[(long long)row * F + j] = r.x; }
        if (row + 1 < N_NODES) { g_xl[(long long)(row + 1) * F + j] = l.y; g_xr[(long long)(row + 1) * F + j] = r.y; }
    }
}

// ---------------- per-edge attention score (pipelined, tiled) ----------------
// score[i] = att . LeakyReLU(xl[src] + xr[dst] + eas[i] @ We); warp owns a tile
// of 32 consecutive CSR slots: indices batch-loaded, attrs read sequentially,
// next edge's loads issued before current edge's 128-instr GEMV.
__global__ void __launch_bounds__(128) k_score(
    const float* __restrict__ We, const float* __restrict__ att) {
    int lane = threadIdx.x & 31;
    u64 w[FE][2];                       // We[k][4*lane .. 4*lane+3], 128 regs
    #pragma unroll
    for (int k = 0; k < FE; k++) {
        float4 wv = *(const float4*)(We + k * F + 4 * lane);
        w[k][0] = pack2(wv.x, wv.y);
        w[k][1] = pack2(wv.z, wv.w);
    }
    float4 at = *(const float4*)(att + 4 * lane);
    int wid = (blockIdx.x * blockDim.x + threadIdx.x) >> 5;
    int nw  = (gridDim.x * blockDim.x) >> 5;

    for (long long base = (long long)wid * 32; base < ET; base += (long long)nw * 32) {
        int n = (int)min((long long)32, (long long)ET - base);
        int src_l = (lane < n) ? g_srcs[base + lane] : 0;
        int dst_l = (lane < n) ? g_dsts[base + lane] : 0;
        float myscore = 0.f;

        // prime the pipeline with edge 0
        int s0 = __shfl_sync(0xffffffffu, src_l, 0);
        int d0 = __shfl_sync(0xffffffffu, dst_l, 0);
        float  a_n  = g_eas[base * FE + lane];
        float4 xl_n = *(const float4*)(g_xl + (long long)s0 * F + 4 * lane);
        float4 xr_n = *(const float4*)(g_xr + (long long)d0 * F + 4 * lane);

        for (int j = 0; j < n; j++) {
            float  a_c  = a_n;
            float4 xl_c = xl_n;
            float4 xr_c = xr_n;
            if (j + 1 < n) {
                int s1 = __shfl_sync(0xffffffffu, src_l, j + 1);
                int d1 = __shfl_sync(0xffffffffu, dst_l, j + 1);
                a_n  = g_eas[(base + j + 1) * FE + lane];
                xl_n = *(const float4*)(g_xl + (long long)s1 * F + 4 * lane);
                xr_n = *(const float4*)(g_xr + (long long)d1 * F + 4 * lane);
            }
            u64 acc0 = pack2(xl_c.x + xr_c.x, xl_c.y + xr_c.y);
            u64 acc1 = pack2(xl_c.z + xr_c.z, xl_c.w + xr_c.w);
            #pragma unroll
            for (int k = 0; k < FE; k++) {
                float ak = __shfl_sync(0xffffffffu, a_c, k);
                u64 ak2 = pack2(ak, ak);
                acc0 = ffma2(ak2, w[k][0], acc0);
                acc1 = ffma2(ak2, w[k][1], acc1);
            }
            float2 s01 = unpack2(acc0);
            float2 s23 = unpack2(acc1);
            float t0 = s01.x > 0.f ? s01.x : SLOPE * s01.x;
            float t1 = s01.y > 0.f ? s01.y : SLOPE * s01.y;
            float t2 = s23.x > 0.f ? s23.x : SLOPE * s23.x;
            float t3 = s23.y > 0.f ? s23.y : SLOPE * s23.y;
            float p = t0 * at.x + t1 * at.y + t2 * at.z + t3 * at.w;
            #pragma unroll
            for (int off = 16; off; off >>= 1) p += __shfl_xor_sync(0xffffffffu, p, off);
            if (lane == j) myscore = p;
        }
        if (lane < n) g_score[base + lane] = myscore;   // coalesced
    }
}

// ---------------- softmax aggregation, two-pass (warp per node) --------------
__global__ void __launch_bounds__(256) k_agg(
    const float* __restrict__ bias, int hout_sel) {
    int wid = (blockIdx.x * blockDim.x + threadIdx.x) >> 5;
    if (wid >= N_NODES) return;
    float* hout = (hout_sel == 1) ? g_hB : g_hA;
    int lane = threadIdx.x & 31;
    int beg = g_rowptr[wid], end = g_rowptr[wid + 1];

    float m = -3.0e38f;
    for (int t = beg + lane; t < end; t += 32) m = fmaxf(m, g_score[t]);
    #pragma unroll
    for (int off = 16; off; off >>= 1) m = fmaxf(m, __shfl_xor_sync(0xffffffffu, m, off));
    float den = 0.f;
    for (int t = beg + lane; t < end; t += 32) den += __expf(g_score[t] - m);
    #pragma unroll
    for (int off = 16; off; off >>= 1) den += __shfl_xor_sync(0xffffffffu, den, off);
    float inv = 1.f / den;

    float4 a0 = make_float4(0.f, 0.f, 0.f, 0.f), a1 = a0, a2 = a0, a3 = a0;
    for (int t = beg; t < end; t += 32) {
        int idx = t + lane;
        bool ok = idx < end;
        float pe = ok ? __expf(g_score[idx] - m) : 0.f;
        int   sr = ok ? g_srcs[idx] : 0;
        int cnt = min(32, end - t);
        int j = 0;
        for (; j + 4 <= cnt; j += 4) {
            float p0 = __shfl_sync(0xffffffffu, pe, j);
            float p1 = __shfl_sync(0xffffffffu, pe, j + 1);
            float p2 = __shfl_sync(0xffffffffu, pe, j + 2);
            float p3 = __shfl_sync(0xffffffffu, pe, j + 3);
            int s0 = __shfl_sync(0xffffffffu, sr, j);
            int s1 = __shfl_sync(0xffffffffu, sr, j + 1);
            int s2 = __shfl_sync(0xffffffffu, sr, j + 2);
            int s3 = __shfl_sync(0xffffffffu, sr, j + 3);
            float4 x0 = *(const float4*)(g_xl + (long long)s0 * F + 4 * lane);
            float4 x1 = *(const float4*)(g_xl + (long long)s1 * F + 4 * lane);
            float4 x2 = *(const float4*)(g_xl + (long long)s2 * F + 4 * lane);
            float4 x3 = *(const float4*)(g_xl + (long long)s3 * F + 4 * lane);
            a0.x += p0 * x0.x; a0.y += p0 * x0.y; a0.z += p0 * x0.z; a0.w += p0 * x0.w;
            a1.x += p1 * x1.x; a1.y += p1 * x1.y; a1.z += p1 * x1.z; a1.w += p1 * x1.w;
            a2.x += p2 * x2.x; a2.y += p2 * x2.y; a2.z += p2 * x2.z; a2.w += p2 * x2.w;
            a3.x += p3 * x3.x; a3.y += p3 * x3.y; a3.z += p3 * x3.z; a3.w += p3 * x3.w;
        }
        for (; j < cnt; j++) {
            float pj = __shfl_sync(0xffffffffu, pe, j);
            int   sj = __shfl_sync(0xffffffffu, sr, j);
            float4 xj = *(const float4*)(g_xl + (long long)sj * F + 4 * lane);
            a0.x += pj * xj.x; a0.y += pj * xj.y; a0.z += pj * xj.z; a0.w += pj * xj.w;
        }
    }
    float4 bi = *(const float4*)(bias + 4 * lane);
    float4 o;
    o.x = fmaxf((a0.x + a1.x + a2.x + a3.x) * inv + bi.x, 0.f);
    o.y = fmaxf((a0.y + a1.y + a2.y + a3.y) * inv + bi.y, 0.f);
    o.z = fmaxf((a0.z + a1.z + a2.z + a3.z) * inv + bi.z, 0.f);
    o.w = fmaxf((a0.w + a1.w + a2.w + a3.w) * inv + bi.w, 0.f);
    *(float4*)(hout + (long long)wid * F + 4 * lane) = o;
}

// ---------------- pool + classifier ----------------------------------------
__global__ void k_gptr(const void* __restrict__ batch) {
    int g = blockIdx.x * blockDim.x + threadIdx.x;
    if (g > NG) return;
    int lo = 0, hi = N_NODES;
    while (lo < hi) {
        int mid = (lo + hi) >> 1;
        if (getIdx(batch, mid) < g) lo = mid + 1; else hi = mid;
    }
    g_gptr[g] = lo;
}

__global__ void __launch_bounds__(128) k_poolg() {
    int g = blockIdx.x;
    int j = threadIdx.x;
    int b = g_gptr[g], e = g_gptr[g + 1];
    float acc = 0.f;
    for (int v = b; v < e; v++) acc += g_hA[(long long)v * F + j];
    float inv = 1.f / fmaxf((float)(e - b), 1.f);
    g_pool[g * F + j] = acc * inv;
}

__global__ void k_final(const float* __restrict__ lw, const float* __restrict__ lb,
                        float* __restrict__ out) {
    int t = blockIdx.x * blockDim.x + threadIdx.x;
    if (t >= NG * NC) return;
    int g = t / NC, cls = t % NC;
    float acc = lb[cls];
    #pragma unroll 8
    for (int c = 0; c < F; c++)
        acc += g_pool[g * F + c] * lw[c * NC + cls];
    out[t] = acc;
}

// ---------------- host -------------------------------------------------------
extern "C" void kernel_launch(void* const* d_in, const int* in_sizes, int n_in,
                              void* d_out, int out_size) {
    (void)in_sizes; (void)n_in; (void)out_size;
    const float* x     = (const float*)d_in[0];
    const void*  ei    = d_in[1];               // int32 or int64 (probed)
    const void*  batch = d_in[2];               // int32 or int64 (probed)
    // d_in[3] = dropout (identity in eval)
    const float* ea   = (const float*)d_in[4];
    const float* Wl   = (const float*)d_in[5];
    const float* bl   = (const float*)d_in[6];
    const float* Wr   = (const float*)d_in[7];
    const float* br   = (const float*)d_in[8];
    const float* We   = (const float*)d_in[9];
    const float* att  = (const float*)d_in[10];
    const float* bias = (const float*)d_in[11];
    const float* lw   = (const float*)d_in[12];
    const float* lb   = (const float*)d_in[13];
    float* out = (float*)d_out;

    k_probe<<<1, 32>>>(ei);
    k_zero<<<(N_NODES + 255) / 256, 256>>>();
    k_deg<<<(N_EDGESC + 255) / 256, 256>>>(ei);
    k_scan<<<1, 1024>>>();
    k_self<<<(N_NODES + 255) / 256, 256>>>();
    k_scatter<<<(N_EDGESC + 255) / 256, 256>>>(ei);
    k_permute<<<4096, 256>>>(ea);
    k_loopcsr<<<(N_NODES * 32 + 255) / 256, 256>>>();

    for (int l = 0; l < 3; l++) {
        int hin  = l;                 // 0: x, 1: hA, 2: hB
        int hout = (l == 1) ? 1 : 0;  // layer0 -> hA, layer1 -> hB, layer2 -> hA
        k_xlxr<<<(N_NODES + 31) / 32, 128>>>(x, hin,
                                             Wl + (size_t)l * F * F, bl + (size_t)l * F,
                                             Wr + (size_t)l * F * F, br + (size_t)l * F);
        k_score<<<2048, 128>>>(We + (size_t)l * FE * F, att + (size_t)l * F);
        k_agg<<<(N_NODES * 32 + 255) / 256, 256>>>(bias + (size_t)l * F, hout);
    }

    k_gptr<<<3, 256>>>(batch);
    k_poolg<<<NG, 128>>>();
    k_final<<<(NG * NC + 127) / 128, 128>>>(lw, lb, out);
}

// round 9
// speedup vs baseline: 1.4139x; 1.4139x over previous
#include <cuda_runtime.h>
#include <cuda_bf16.h>

#define N_NODES  50000
#define N_EDGESC 1600000
#define ET       1650000            // edges + self loops
#define F        128
#define FE       32
#define NG       512
#define NC       10
#define SLOPE    0.2f

typedef unsigned long long u64;

// ---------------- f32x2 helpers (Blackwell packed fp32) ----------------------
__device__ __forceinline__ u64 pack2(float x, float y) {
    u64 r; asm("mov.b64 %0, {%1, %2};" : "=l"(r) : "f"(x), "f"(y)); return r;
}
__device__ __forceinline__ float2 unpack2(u64 v) {
    float2 f; asm("mov.b64 {%0, %1}, %2;" : "=f"(f.x), "=f"(f.y) : "l"(v)); return f;
}
__device__ __forceinline__ u64 ffma2(u64 a, u64 b, u64 c) {
    u64 d; asm("fma.rn.f32x2 %0, %1, %2, %3;" : "=l"(d) : "l"(a), "l"(b), "l"(c)); return d;
}

// ---------------- scratch (device globals: allocation-free rule) -------------
__device__ float g_eas[(size_t)ET * FE];   // edge attrs in CSR slot order (211MB)
__device__ float g_score[ET];
__device__ float g_xl[(size_t)N_NODES * F];
__device__ float g_xr[(size_t)N_NODES * F];
__device__ float g_hA[(size_t)N_NODES * F];
__device__ float g_hB[(size_t)N_NODES * F];
__device__ int   g_deg[N_NODES];
__device__ int   g_rowptr[N_NODES + 1];
__device__ int   g_cnt[N_NODES];
__device__ int   g_srcs[ET];
__device__ int   g_dsts[ET];
__device__ int   g_slot[N_EDGESC];         // CSR slot of original edge e
__device__ int   g_gptr[NG + 1];
__device__ float g_pool[NG * F];
__device__ int   g_is64;

// ---------------- index dtype handling --------------------------------------
__device__ __forceinline__ int getIdx(const void* __restrict__ p, long long i) {
    if (g_is64) return (int)((const long long*)p)[i];
    return ((const int*)p)[i];
}

// probe dtype + zero counters (merged)
__global__ void k_probe_zero(const void* __restrict__ ei) {
    int i = blockIdx.x * blockDim.x + threadIdx.x;
    if (i == 0) {
        const unsigned* w = (const unsigned*)ei;
        int all0 = 1;
        #pragma unroll
        for (int k = 0; k < 64; k++) all0 &= (w[2 * k + 1] == 0u);
        g_is64 = all0;
    }
    if (i < N_NODES) { g_deg[i] = 0; g_cnt[i] = 0; }
}

__global__ void k_deg(const void* __restrict__ ei) {
    int e = blockIdx.x * blockDim.x + threadIdx.x;
    if (e >= N_EDGESC) return;
    atomicAdd(&g_deg[getIdx(ei, (long long)N_EDGESC + e)], 1);
}

// exclusive scan of (deg+1) -> rowptr, then self-loop slots (fused)
__global__ void k_scan() {
    __shared__ int sw[32];
    __shared__ int sc;
    int tid = threadIdx.x, lane = tid & 31, wid = tid >> 5;
    if (tid == 0) sc = 0;
    __syncthreads();
    for (int base = 0; base < N_NODES; base += 1024) {
        int idx = base + tid;
        int orig = (idx < N_NODES) ? (g_deg[idx] + 1) : 0;
        int v = orig;
        #pragma unroll
        for (int off = 1; off < 32; off <<= 1) {
            int t = __shfl_up_sync(0xffffffffu, v, off);
            if (lane >= off) v += t;
        }
        if (lane == 31) sw[wid] = v;
        __syncthreads();
        if (wid == 0) {
            int w = sw[lane];
            #pragma unroll
            for (int off = 1; off < 32; off <<= 1) {
                int t = __shfl_up_sync(0xffffffffu, w, off);
                if (lane >= off) w += t;
            }
            sw[lane] = w;
        }
        __syncthreads();
        int c0 = sc;
        int incl = v + (wid ? sw[wid - 1] : 0);
        if (idx < N_NODES) g_rowptr[idx] = c0 + incl - orig;
        int tot = sw[31];
        __syncthreads();
        if (tid == 0) sc = c0 + tot;
        __syncthreads();
    }
    if (tid == 0) g_rowptr[N_NODES] = sc;   // == ET
    __syncthreads();
    // self-loops occupy slot rowptr[v] of each row
    for (int v = tid; v < N_NODES; v += 1024) {
        int p = g_rowptr[v];
        g_srcs[p] = v;
        g_dsts[p] = v;
    }
}

// counting-sort scatter of real edges by dst; records inverse permutation
__global__ void k_scatter(const void* __restrict__ ei) {
    int e = blockIdx.x * blockDim.x + threadIdx.x;
    if (e >= N_EDGESC) return;
    int src = getIdx(ei, e);
    int dst = getIdx(ei, (long long)N_EDGESC + e);
    int p = g_rowptr[dst] + 1 + atomicAdd(&g_cnt[dst], 1);
    g_srcs[p] = src;
    g_dsts[p] = dst;
    g_slot[e] = p;
}

// permute attrs into CSR order: sequential reads, scattered writes (no stalls)
__global__ void __launch_bounds__(256) k_permute(const float* __restrict__ ea) {
    int wid = (blockIdx.x * blockDim.x + threadIdx.x) >> 5;
    int nw  = (gridDim.x * blockDim.x) >> 5;
    int lane = threadIdx.x & 31;
    for (int e = wid; e < N_EDGESC; e += nw) {
        float v = ea[(long long)e * FE + lane];
        g_eas[(long long)g_slot[e] * FE + lane] = v;
    }
}

// self-loop attr = mean of incoming attrs (contiguous reads in CSR order)
__global__ void __launch_bounds__(256) k_loopcsr() {
    int wid = (blockIdx.x * blockDim.x + threadIdx.x) >> 5;
    if (wid >= N_NODES) return;
    int lane = threadIdx.x & 31;
    int beg = g_rowptr[wid], end = g_rowptr[wid + 1];
    float acc = 0.f;
    #pragma unroll 4
    for (int i = beg + 1; i < end; i++)
        acc += g_eas[(long long)i * FE + lane];
    float d = (float)(end - beg - 1);
    g_eas[(long long)beg * FE + lane] = acc / fmaxf(d, 1.f);
}

// ---------------- node GEMMs: xl = h@Wl + bl, xr = h@Wr + br ------------------
__global__ void __launch_bounds__(128) k_xlxr(
    const float* __restrict__ x_ext, int hin_sel,
    const float* __restrict__ Wl, const float* __restrict__ bl,
    const float* __restrict__ Wr, const float* __restrict__ br) {
    const float* h = (hin_sel == 0) ? x_ext : (hin_sel == 1 ? g_hA : g_hB);
    __shared__ float shT[F][34];
    int j = threadIdx.x;
    int r0 = blockIdx.x * 32;
    #pragma unroll
    for (int r = 0; r < 32; r++) {
        int row = r0 + r;
        shT[j][r] = (row < N_NODES) ? h[(long long)row * F + j] : 0.f;
    }
    __syncthreads();
    u64 aL[16], aR[16];
    {
        u64 bl2 = pack2(bl[j], bl[j]);
        u64 br2 = pack2(br[j], br[j]);
        #pragma unroll
        for (int rp = 0; rp < 16; rp++) { aL[rp] = bl2; aR[rp] = br2; }
    }
    #pragma unroll 2
    for (int k = 0; k < F; k++) {
        float wl = Wl[k * F + j];
        float wr = Wr[k * F + j];
        u64 wl2 = pack2(wl, wl);
        u64 wr2 = pack2(wr, wr);
        #pragma unroll
        for (int rp = 0; rp < 16; rp++) {
            u64 hv2 = *(const u64*)&shT[k][2 * rp];
            aL[rp] = ffma2(hv2, wl2, aL[rp]);
            aR[rp] = ffma2(hv2, wr2, aR[rp]);
        }
    }
    #pragma unroll
    for (int rp = 0; rp < 16; rp++) {
        float2 l = unpack2(aL[rp]);
        float2 r = unpack2(aR[rp]);
        int row = r0 + 2 * rp;
        if (row < N_NODES)     { g_xl[(long long)row * F + j] = l.x; g_xr[(long long)row * F + j] = r.x; }
        if (row + 1 < N_NODES) { g_xl[(long long)(row + 1) * F + j] = l.y; g_xr[(long long)(row + 1) * F + j] = r.y; }
    }
}

// ---------------- per-edge attention score (smem-staged tiles) ---------------
// Warp owns 32 consecutive CSR slots. Attrs staged to smem with 32 independent
// coalesced loads; the 32x128 GEMV then reads a_k via LDS broadcast (no shfl
// dependency chain). Weights register-resident; xl/xr prefetched one edge ahead.
#define SC_WARPS 8
__global__ void __launch_bounds__(32 * SC_WARPS) k_score(
    const float* __restrict__ We, const float* __restrict__ att) {
    __shared__ float sa[SC_WARPS][32][32];
    int lane = threadIdx.x & 31;
    int wib  = threadIdx.x >> 5;
    u64 w[FE][2];
    #pragma unroll
    for (int k = 0; k < FE; k++) {
        float4 wv = *(const float4*)(We + k * F + 4 * lane);
        w[k][0] = pack2(wv.x, wv.y);
        w[k][1] = pack2(wv.z, wv.w);
    }
    float4 at = *(const float4*)(att + 4 * lane);

    int tile = blockIdx.x * SC_WARPS + wib;
    int ntiles = (ET + 31) / 32;
    if (tile >= ntiles) return;
    long long base = (long long)tile * 32;
    int n = (int)min((long long)32, (long long)ET - base);

    int src_l = (lane < n) ? g_srcs[base + lane] : 0;
    int dst_l = (lane < n) ? g_dsts[base + lane] : 0;

    // stage attrs: 32 independent coalesced 128B loads
    for (int j = 0; j < n; j++)
        sa[wib][j][lane] = g_eas[(base + j) * FE + lane];
    __syncwarp();

    float myscore = 0.f;
    // prime pipeline with edge 0
    int s0 = __shfl_sync(0xffffffffu, src_l, 0);
    int d0 = __shfl_sync(0xffffffffu, dst_l, 0);
    float4 xl_n = *(const float4*)(g_xl + (long long)s0 * F + 4 * lane);
    float4 xr_n = *(const float4*)(g_xr + (long long)d0 * F + 4 * lane);

    for (int j = 0; j < n; j++) {
        float4 xl_c = xl_n, xr_c = xr_n;
        if (j + 1 < n) {
            int s1 = __shfl_sync(0xffffffffu, src_l, j + 1);
            int d1 = __shfl_sync(0xffffffffu, dst_l, j + 1);
            xl_n = *(const float4*)(g_xl + (long long)s1 * F + 4 * lane);
            xr_n = *(const float4*)(g_xr + (long long)d1 * F + 4 * lane);
        }
        u64 acc0 = pack2(xl_c.x + xr_c.x, xl_c.y + xr_c.y);
        u64 acc1 = pack2(xl_c.z + xr_c.z, xl_c.w + xr_c.w);
        #pragma unroll
        for (int k = 0; k < FE; k++) {
            float ak = sa[wib][j][k];          // LDS broadcast, no shfl chain
            u64 ak2 = pack2(ak, ak);
            acc0 = ffma2(ak2, w[k][0], acc0);
            acc1 = ffma2(ak2, w[k][1], acc1);
        }
        float2 s01 = unpack2(acc0);
        float2 s23 = unpack2(acc1);
        float t0 = s01.x > 0.f ? s01.x : SLOPE * s01.x;
        float t1 = s01.y > 0.f ? s01.y : SLOPE * s01.y;
        float t2 = s23.x > 0.f ? s23.x : SLOPE * s23.x;
        float t3 = s23.y > 0.f ? s23.y : SLOPE * s23.y;
        float p = t0 * at.x + t1 * at.y + t2 * at.z + t3 * at.w;
        #pragma unroll
        for (int off = 16; off; off >>= 1) p += __shfl_xor_sync(0xffffffffu, p, off);
        if (lane == j) myscore = p;
    }
    if (lane < n) g_score[base + lane] = myscore;   // coalesced
}

// ---------------- softmax aggregation, two-pass (warp per node) --------------
__global__ void __launch_bounds__(256) k_agg(
    const float* __restrict__ bias, int hout_sel) {
    int wid = (blockIdx.x * blockDim.x + threadIdx.x) >> 5;
    if (wid >= N_NODES) return;
    float* hout = (hout_sel == 1) ? g_hB : g_hA;
    int lane = threadIdx.x & 31;
    int beg = g_rowptr[wid], end = g_rowptr[wid + 1];

    float m = -3.0e38f;
    for (int t = beg + lane; t < end; t += 32) m = fmaxf(m, g_score[t]);
    #pragma unroll
    for (int off = 16; off; off >>= 1) m = fmaxf(m, __shfl_xor_sync(0xffffffffu, m, off));
    float den = 0.f;
    for (int t = beg + lane; t < end; t += 32) den += __expf(g_score[t] - m);
    #pragma unroll
    for (int off = 16; off; off >>= 1) den += __shfl_xor_sync(0xffffffffu, den, off);
    float inv = 1.f / den;

    float4 a0 = make_float4(0.f, 0.f, 0.f, 0.f), a1 = a0, a2 = a0, a3 = a0;
    for (int t = beg; t < end; t += 32) {
        int idx = t + lane;
        bool ok = idx < end;
        float pe = ok ? __expf(g_score[idx] - m) : 0.f;
        int   sr = ok ? g_srcs[idx] : 0;
        int cnt = min(32, end - t);
        int j = 0;
        for (; j + 4 <= cnt; j += 4) {
            float p0 = __shfl_sync(0xffffffffu, pe, j);
            float p1 = __shfl_sync(0xffffffffu, pe, j + 1);
            float p2 = __shfl_sync(0xffffffffu, pe, j + 2);
            float p3 = __shfl_sync(0xffffffffu, pe, j + 3);
            int s0 = __shfl_sync(0xffffffffu, sr, j);
            int s1 = __shfl_sync(0xffffffffu, sr, j + 1);
            int s2 = __shfl_sync(0xffffffffu, sr, j + 2);
            int s3 = __shfl_sync(0xffffffffu, sr, j + 3);
            float4 x0 = *(const float4*)(g_xl + (long long)s0 * F + 4 * lane);
            float4 x1 = *(const float4*)(g_xl + (long long)s1 * F + 4 * lane);
            float4 x2 = *(const float4*)(g_xl + (long long)s2 * F + 4 * lane);
            float4 x3 = *(const float4*)(g_xl + (long long)s3 * F + 4 * lane);
            a0.x += p0 * x0.x; a0.y += p0 * x0.y; a0.z += p0 * x0.z; a0.w += p0 * x0.w;
            a1.x += p1 * x1.x; a1.y += p1 * x1.y; a1.z += p1 * x1.z; a1.w += p1 * x1.w;
            a2.x += p2 * x2.x; a2.y += p2 * x2.y; a2.z += p2 * x2.z; a2.w += p2 * x2.w;
            a3.x += p3 * x3.x; a3.y += p3 * x3.y; a3.z += p3 * x3.z; a3.w += p3 * x3.w;
        }
        for (; j < cnt; j++) {
            float pj = __shfl_sync(0xffffffffu, pe, j);
            int   sj = __shfl_sync(0xffffffffu, sr, j);
            float4 xj = *(const float4*)(g_xl + (long long)sj * F + 4 * lane);
            a0.x += pj * xj.x; a0.y += pj * xj.y; a0.z += pj * xj.z; a0.w += pj * xj.w;
        }
    }
    float4 bi = *(const float4*)(bias + 4 * lane);
    float4 o;
    o.x = fmaxf((a0.x + a1.x + a2.x + a3.x) * inv + bi.x, 0.f);
    o.y = fmaxf((a0.y + a1.y + a2.y + a3.y) * inv + bi.y, 0.f);
    o.z = fmaxf((a0.z + a1.z + a2.z + a3.z) * inv + bi.z, 0.f);
    o.w = fmaxf((a0.w + a1.w + a2.w + a3.w) * inv + bi.w, 0.f);
    *(float4*)(hout + (long long)wid * F + 4 * lane) = o;
}

// ---------------- pool + classifier ----------------------------------------
__global__ void k_gptr(const void* __restrict__ batch) {
    int g = blockIdx.x * blockDim.x + threadIdx.x;
    if (g > NG) return;
    int lo = 0, hi = N_NODES;
    while (lo < hi) {
        int mid = (lo + hi) >> 1;
        if (getIdx(batch, mid) < g) lo = mid + 1; else hi = mid;
    }
    g_gptr[g] = lo;
}

__global__ void __launch_bounds__(128) k_poolg() {
    int g = blockIdx.x;
    int j = threadIdx.x;
    int b = g_gptr[g], e = g_gptr[g + 1];
    float acc = 0.f;
    for (int v = b; v < e; v++) acc += g_hA[(long long)v * F + j];
    float inv = 1.f / fmaxf((float)(e - b), 1.f);
    g_pool[g * F + j] = acc * inv;
}

__global__ void k_final(const float* __restrict__ lw, const float* __restrict__ lb,
                        float* __restrict__ out) {
    int t = blockIdx.x * blockDim.x + threadIdx.x;
    if (t >= NG * NC) return;
    int g = t / NC, cls = t % NC;
    float acc = lb[cls];
    #pragma unroll 8
    for (int c = 0; c < F; c++)
        acc += g_pool[g * F + c] * lw[c * NC + cls];
    out[t] = acc;
}

// ---------------- host -------------------------------------------------------
extern "C" void kernel_launch(void* const* d_in, const int* in_sizes, int n_in,
                              void* d_out, int out_size) {
    (void)in_sizes; (void)n_in; (void)out_size;
    const float* x     = (const float*)d_in[0];
    const void*  ei    = d_in[1];               // int32 or int64 (probed)
    const void*  batch = d_in[2];               // int32 or int64 (probed)
    // d_in[3] = dropout (identity in eval)
    const float* ea   = (const float*)d_in[4];
    const float* Wl   = (const float*)d_in[5];
    const float* bl   = (const float*)d_in[6];
    const float* Wr   = (const float*)d_in[7];
    const float* br   = (const float*)d_in[8];
    const float* We   = (const float*)d_in[9];
    const float* att  = (const float*)d_in[10];
    const float* bias = (const float*)d_in[11];
    const float* lw   = (const float*)d_in[12];
    const float* lb   = (const float*)d_in[13];
    float* out = (float*)d_out;

    k_probe_zero<<<(N_NODES + 255) / 256, 256>>>(ei);
    k_deg<<<(N_EDGESC + 255) / 256, 256>>>(ei);
    k_scan<<<1, 1024>>>();
    k_scatter<<<(N_EDGESC + 255) / 256, 256>>>(ei);
    k_permute<<<4096, 256>>>(ea);
    k_loopcsr<<<(N_NODES * 32 + 255) / 256, 256>>>();

    int ntiles = (ET + 31) / 32;
    for (int l = 0; l < 3; l++) {
        int hin  = l;                 // 0: x, 1: hA, 2: hB
        int hout = (l == 1) ? 1 : 0;  // layer0 -> hA, layer1 -> hB, layer2 -> hA
        k_xlxr<<<(N_NODES + 31) / 32, 128>>>(x, hin,
                                             Wl + (size_t)l * F * F, bl + (size_t)l * F,
                                             Wr + (size_t)l * F * F, br + (size_t)l * F);
        k_score<<<(ntiles + SC_WARPS - 1) / SC_WARPS, 32 * SC_WARPS>>>(
            We + (size_t)l * FE * F, att + (size_t)l * F);
        k_agg<<<(N_NODES * 32 + 255) / 256, 256>>>(bias + (size_t)l * F, hout);
    }

    k_gptr<<<3, 256>>>(batch);
    k_poolg<<<NG, 128>>>();
    k_final<<<(NG * NC + 127) / 128, 128>>>(lw, lb, out);
}

// round 10
// speedup vs baseline: 1.4725x; 1.0414x over previous
#include <cuda_runtime.h>
#include <cuda_bf16.h>

#define N_NODES  50000
#define N_EDGESC 1600000
#define ET       1650000            // edges + self loops
#define F        128
#define FE       32
#define NG       512
#define NC       10
#define SLOPE    0.2f
#define SCAN_NB  ((N_NODES + 1023) / 1024)   // 49

typedef unsigned long long u64;

// ---------------- f32x2 helpers (Blackwell packed fp32) ----------------------
__device__ __forceinline__ u64 pack2(float x, float y) {
    u64 r; asm("mov.b64 %0, {%1, %2};" : "=l"(r) : "f"(x), "f"(y)); return r;
}
__device__ __forceinline__ float2 unpack2(u64 v) {
    float2 f; asm("mov.b64 {%0, %1}, %2;" : "=f"(f.x), "=f"(f.y) : "l"(v)); return f;
}
__device__ __forceinline__ u64 ffma2(u64 a, u64 b, u64 c) {
    u64 d; asm("fma.rn.f32x2 %0, %1, %2, %3;" : "=l"(d) : "l"(a), "l"(b), "l"(c)); return d;
}

// ---------------- scratch (device globals: allocation-free rule) -------------
__device__ float g_eas[(size_t)ET * FE];   // edge attrs in CSR slot order (211MB)
__device__ float g_score[ET];
__device__ float g_xl[(size_t)N_NODES * F];
__device__ float g_xr[(size_t)N_NODES * F];
__device__ float g_hA[(size_t)N_NODES * F];
__device__ float g_hB[(size_t)N_NODES * F];
__device__ int   g_deg[N_NODES];
__device__ int   g_rowptr[N_NODES + 1];
__device__ int   g_cnt[N_NODES];
__device__ int   g_srcs[ET];
__device__ int   g_dsts[ET];
__device__ int   g_slot[N_EDGESC];
__device__ int   g_bsum[64];
__device__ int   g_boff[64];
__device__ int   g_gptr[NG + 1];
__device__ float g_pool[NG * F];
__device__ int   g_is64;

// ---------------- index dtype handling --------------------------------------
__device__ __forceinline__ int getIdx(const void* __restrict__ p, long long i) {
    if (g_is64) return (int)((const long long*)p)[i];
    return ((const int*)p)[i];
}

__global__ void k_probe_zero(const void* __restrict__ ei) {
    int i = blockIdx.x * blockDim.x + threadIdx.x;
    if (i == 0) {
        const unsigned* w = (const unsigned*)ei;
        int all0 = 1;
        #pragma unroll
        for (int k = 0; k < 64; k++) all0 &= (w[2 * k + 1] == 0u);
        g_is64 = all0;
    }
    if (i < N_NODES) { g_deg[i] = 0; g_cnt[i] = 0; }
}

__global__ void k_deg(const void* __restrict__ ei) {
    int e = blockIdx.x * blockDim.x + threadIdx.x;
    if (e >= N_EDGESC) return;
    atomicAdd(&g_deg[getIdx(ei, (long long)N_EDGESC + e)], 1);
}

// ---- 3-kernel parallel exclusive scan of (deg+1) --------------------------
__global__ void k_scanA() {
    __shared__ int sw[32];
    int tid = threadIdx.x, lane = tid & 31, wid = tid >> 5;
    int idx = blockIdx.x * 1024 + tid;
    int orig = (idx < N_NODES) ? (g_deg[idx] + 1) : 0;
    int v = orig;
    #pragma unroll
    for (int off = 1; off < 32; off <<= 1) {
        int t = __shfl_up_sync(0xffffffffu, v, off);
        if (lane >= off) v += t;
    }
    if (lane == 31) sw[wid] = v;
    __syncthreads();
    if (wid == 0) {
        int w = sw[lane];
        #pragma unroll
        for (int off = 1; off < 32; off <<= 1) {
            int t = __shfl_up_sync(0xffffffffu, w, off);
            if (lane >= off) w += t;
        }
        sw[lane] = w;
    }
    __syncthreads();
    int incl = v + (wid ? sw[wid - 1] : 0);
    if (idx < N_NODES) g_rowptr[idx] = incl - orig;   // block-local exclusive
    if (tid == 1023) g_bsum[blockIdx.x] = incl;
}

__global__ void k_scanB() {       // one warp: exclusive scan of block sums
    int lane = threadIdx.x;
    int v0 = (lane < SCAN_NB) ? g_bsum[lane] : 0;
    int i0 = v0;
    #pragma unroll
    for (int off = 1; off < 32; off <<= 1) {
        int t = __shfl_up_sync(0xffffffffu, i0, off);
        if (lane >= off) i0 += t;
    }
    int tot0 = __shfl_sync(0xffffffffu, i0, 31);
    if (lane < SCAN_NB) g_boff[lane] = i0 - v0;
    int j = 32 + lane;
    int v1 = (j < SCAN_NB) ? g_bsum[j] : 0;
    int i1 = v1;
    #pragma unroll
    for (int off = 1; off < 32; off <<= 1) {
        int t = __shfl_up_sync(0xffffffffu, i1, off);
        if (lane >= off) i1 += t;
    }
    if (j < SCAN_NB) g_boff[j] = tot0 + i1 - v1;
}

__global__ void k_scanC() {       // add offsets + self-loop slots
    int idx = blockIdx.x * blockDim.x + threadIdx.x;
    if (idx == 0) g_rowptr[N_NODES] = ET;
    if (idx >= N_NODES) return;
    int p = g_rowptr[idx] + g_boff[idx >> 10];
    g_rowptr[idx] = p;
    g_srcs[p] = idx;
    g_dsts[p] = idx;
}

// counting-sort scatter of real edges by dst; records inverse permutation
__global__ void k_scatter(const void* __restrict__ ei) {
    int e = blockIdx.x * blockDim.x + threadIdx.x;
    if (e >= N_EDGESC) return;
    int src = getIdx(ei, e);
    int dst = getIdx(ei, (long long)N_EDGESC + e);
    int p = g_rowptr[dst] + 1 + atomicAdd(&g_cnt[dst], 1);
    g_srcs[p] = src;
    g_dsts[p] = dst;
    g_slot[e] = p;
}

// permute attrs into CSR order: sequential reads x4 (MLP=4), scattered writes
__global__ void __launch_bounds__(256) k_permute(const float* __restrict__ ea) {
    int wid = (blockIdx.x * blockDim.x + threadIdx.x) >> 5;
    int nw  = (gridDim.x * blockDim.x) >> 5;
    int lane = threadIdx.x & 31;
    for (int e = wid * 4; e < N_EDGESC; e += nw * 4) {
        float v0 = ea[(long long)(e + 0) * FE + lane];
        float v1 = ea[(long long)(e + 1) * FE + lane];
        float v2 = ea[(long long)(e + 2) * FE + lane];
        float v3 = ea[(long long)(e + 3) * FE + lane];
        int s0 = g_slot[e + 0], s1 = g_slot[e + 1];
        int s2 = g_slot[e + 2], s3 = g_slot[e + 3];
        g_eas[(long long)s0 * FE + lane] = v0;
        g_eas[(long long)s1 * FE + lane] = v1;
        g_eas[(long long)s2 * FE + lane] = v2;
        g_eas[(long long)s3 * FE + lane] = v3;
    }
}

// self-loop attr = mean of incoming attrs (contiguous reads, dual accumulators)
__global__ void __launch_bounds__(256) k_loopcsr() {
    int wid = (blockIdx.x * blockDim.x + threadIdx.x) >> 5;
    if (wid >= N_NODES) return;
    int lane = threadIdx.x & 31;
    int beg = g_rowptr[wid], end = g_rowptr[wid + 1];
    float acc0 = 0.f, acc1 = 0.f;
    int i = beg + 1;
    for (; i + 1 < end; i += 2) {
        acc0 += g_eas[(long long)i * FE + lane];
        acc1 += g_eas[(long long)(i + 1) * FE + lane];
    }
    if (i < end) acc0 += g_eas[(long long)i * FE + lane];
    float d = (float)(end - beg - 1);
    g_eas[(long long)beg * FE + lane] = (acc0 + acc1) / fmaxf(d, 1.f);
}

// ---------------- node GEMMs: xl = h@Wl + bl, xr = h@Wr + br ------------------
__global__ void __launch_bounds__(128) k_xlxr(
    const float* __restrict__ x_ext, int hin_sel,
    const float* __restrict__ Wl, const float* __restrict__ bl,
    const float* __restrict__ Wr, const float* __restrict__ br) {
    const float* h = (hin_sel == 0) ? x_ext : (hin_sel == 1 ? g_hA : g_hB);
    __shared__ float shT[F][34];
    int j = threadIdx.x;
    int r0 = blockIdx.x * 32;
    #pragma unroll
    for (int r = 0; r < 32; r++) {
        int row = r0 + r;
        shT[j][r] = (row < N_NODES) ? h[(long long)row * F + j] : 0.f;
    }
    __syncthreads();
    u64 aL[16], aR[16];
    {
        u64 bl2 = pack2(bl[j], bl[j]);
        u64 br2 = pack2(br[j], br[j]);
        #pragma unroll
        for (int rp = 0; rp < 16; rp++) { aL[rp] = bl2; aR[rp] = br2; }
    }
    #pragma unroll 2
    for (int k = 0; k < F; k++) {
        float wl = Wl[k * F + j];
        float wr = Wr[k * F + j];
        u64 wl2 = pack2(wl, wl);
        u64 wr2 = pack2(wr, wr);
        #pragma unroll
        for (int rp = 0; rp < 16; rp++) {
            u64 hv2 = *(const u64*)&shT[k][2 * rp];
            aL[rp] = ffma2(hv2, wl2, aL[rp]);
            aR[rp] = ffma2(hv2, wr2, aR[rp]);
        }
    }
    #pragma unroll
    for (int rp = 0; rp < 16; rp++) {
        float2 l = unpack2(aL[rp]);
        float2 r = unpack2(aR[rp]);
        int row = r0 + 2 * rp;
        if (row < N_NODES)     { g_xl[(long long)row * F + j] = l.x; g_xr[(long long)row * F + j] = r.x; }
        if (row + 1 < N_NODES) { g_xl[(long long)(row + 1) * F + j] = l.y; g_xr[(long long)(row + 1) * F + j] = r.y; }
    }
}

// ---------------- per-edge attention score (duplicated-pair smem) ------------
#define SC_WARPS 4
__device__ __forceinline__ float edge_score(
    const float2* __restrict__ sarow, float4 xl, float4 xr, float4 at,
    const u64 (* __restrict__ w)[2]) {
    u64 acc0 = pack2(xl.x + xr.x, xl.y + xr.y);
    u64 acc1 = pack2(xl.z + xr.z, xl.w + xr.w);
    const float4* sp = (const float4*)sarow;   // (a2k,a2k,a2k+1,a2k+1)
    #pragma unroll
    for (int kk = 0; kk < FE / 2; kk++) {
        float4 q = sp[kk];                      // uniform LDS.128 broadcast
        u64 lo = pack2(q.x, q.y);               // reg-pair rename
        u64 hi = pack2(q.z, q.w);
        acc0 = ffma2(lo, w[2 * kk][0], acc0);
        acc1 = ffma2(lo, w[2 * kk][1], acc1);
        acc0 = ffma2(hi, w[2 * kk + 1][0], acc0);
        acc1 = ffma2(hi, w[2 * kk + 1][1], acc1);
    }
    float2 s01 = unpack2(acc0);
    float2 s23 = unpack2(acc1);
    float t0 = s01.x > 0.f ? s01.x : SLOPE * s01.x;
    float t1 = s01.y > 0.f ? s01.y : SLOPE * s01.y;
    float t2 = s23.x > 0.f ? s23.x : SLOPE * s23.x;
    float t3 = s23.y > 0.f ? s23.y : SLOPE * s23.y;
    float p = t0 * at.x + t1 * at.y + t2 * at.z + t3 * at.w;
    #pragma unroll
    for (int off = 16; off; off >>= 1) p += __shfl_xor_sync(0xffffffffu, p, off);
    return p;
}

__global__ void __launch_bounds__(32 * SC_WARPS) k_score(
    const float* __restrict__ We, const float* __restrict__ att) {
    __shared__ float2 sa[SC_WARPS][32][32];    // 32KB static
    int lane = threadIdx.x & 31;
    int wib  = threadIdx.x >> 5;
    u64 w[FE][2];
    #pragma unroll
    for (int k = 0; k < FE; k++) {
        float4 wv = *(const float4*)(We + k * F + 4 * lane);
        w[k][0] = pack2(wv.x, wv.y);
        w[k][1] = pack2(wv.z, wv.w);
    }
    float4 at = *(const float4*)(att + 4 * lane);

    int tile = blockIdx.x * SC_WARPS + wib;
    int ntiles = (ET + 31) / 32;
    if (tile >= ntiles) return;
    long long base = (long long)tile * 32;
    int n = (int)min((long long)32, (long long)ET - base);

    int src_l = (lane < n) ? g_srcs[base + lane] : 0;
    int dst_l = (lane < n) ? g_dsts[base + lane] : 0;

    for (int j = 0; j < n; j++) {
        float v = g_eas[(base + j) * FE + lane];
        sa[wib][j][lane] = make_float2(v, v);   // duplicated pair
    }
    __syncwarp();

    float myscore = 0.f;
    float4 xlA, xrA, xlB, xrB;
    {
        int s = __shfl_sync(0xffffffffu, src_l, 0);
        int d = __shfl_sync(0xffffffffu, dst_l, 0);
        xlA = *(const float4*)(g_xl + (long long)s * F + 4 * lane);
        xrA = *(const float4*)(g_xr + (long long)d * F + 4 * lane);
    }
    if (n > 1) {
        int s = __shfl_sync(0xffffffffu, src_l, 1);
        int d = __shfl_sync(0xffffffffu, dst_l, 1);
        xlB = *(const float4*)(g_xl + (long long)s * F + 4 * lane);
        xrB = *(const float4*)(g_xr + (long long)d * F + 4 * lane);
    }

    int j = 0;
    while (j < n) {
        // edge j (slot A); prefetch j+2 into A
        {
            float4 xl_c = xlA, xr_c = xrA;
            if (j + 2 < n) {
                int s = __shfl_sync(0xffffffffu, src_l, j + 2);
                int d = __shfl_sync(0xffffffffu, dst_l, j + 2);
                xlA = *(const float4*)(g_xl + (long long)s * F + 4 * lane);
                xrA = *(const float4*)(g_xr + (long long)d * F + 4 * lane);
            }
            float p = edge_score(sa[wib][j], xl_c, xr_c, at, w);
            if (lane == j) myscore = p;
        }
        j++;
        if (j >= n) break;
        // edge j (slot B); prefetch j+2 into B
        {
            float4 xl_c = xlB, xr_c = xrB;
            if (j + 2 < n) {
                int s = __shfl_sync(0xffffffffu, src_l, j + 2);
                int d = __shfl_sync(0xffffffffu, dst_l, j + 2);
                xlB = *(const float4*)(g_xl + (long long)s * F + 4 * lane);
                xrB = *(const float4*)(g_xr + (long long)d * F + 4 * lane);
            }
            float p = edge_score(sa[wib][j], xl_c, xr_c, at, w);
            if (lane == j) myscore = p;
        }
        j++;
    }
    if (lane < n) g_score[base + lane] = myscore;   // coalesced
}

// ---------------- softmax aggregation, two-pass (warp per node) --------------
__global__ void __launch_bounds__(256) k_agg(
    const float* __restrict__ bias, int hout_sel) {
    int wid = (blockIdx.x * blockDim.x + threadIdx.x) >> 5;
    if (wid >= N_NODES) return;
    float* hout = (hout_sel == 1) ? g_hB : g_hA;
    int lane = threadIdx.x & 31;
    int beg = g_rowptr[wid], end = g_rowptr[wid + 1];

    float m = -3.0e38f;
    for (int t = beg + lane; t < end; t += 32) m = fmaxf(m, g_score[t]);
    #pragma unroll
    for (int off = 16; off; off >>= 1) m = fmaxf(m, __shfl_xor_sync(0xffffffffu, m, off));
    float den = 0.f;
    for (int t = beg + lane; t < end; t += 32) den += __expf(g_score[t] - m);
    #pragma unroll
    for (int off = 16; off; off >>= 1) den += __shfl_xor_sync(0xffffffffu, den, off);
    float inv = 1.f / den;

    float4 a0 = make_float4(0.f, 0.f, 0.f, 0.f), a1 = a0, a2 = a0, a3 = a0;
    for (int t = beg; t < end; t += 32) {
        int idx = t + lane;
        bool ok = idx < end;
        float pe = ok ? __expf(g_score[idx] - m) : 0.f;
        int   sr = ok ? g_srcs[idx] : 0;
        int cnt = min(32, end - t);
        int j = 0;
        for (; j + 4 <= cnt; j += 4) {
            float p0 = __shfl_sync(0xffffffffu, pe, j);
            float p1 = __shfl_sync(0xffffffffu, pe, j + 1);
            float p2 = __shfl_sync(0xffffffffu, pe, j + 2);
            float p3 = __shfl_sync(0xffffffffu, pe, j + 3);
            int s0 = __shfl_sync(0xffffffffu, sr, j);
            int s1 = __shfl_sync(0xffffffffu, sr, j + 1);
            int s2 = __shfl_sync(0xffffffffu, sr, j + 2);
            int s3 = __shfl_sync(0xffffffffu, sr, j + 3);
            float4 x0 = *(const float4*)(g_xl + (long long)s0 * F + 4 * lane);
            float4 x1 = *(const float4*)(g_xl + (long long)s1 * F + 4 * lane);
            float4 x2 = *(const float4*)(g_xl + (long long)s2 * F + 4 * lane);
            float4 x3 = *(const float4*)(g_xl + (long long)s3 * F + 4 * lane);
            a0.x += p0 * x0.x; a0.y += p0 * x0.y; a0.z += p0 * x0.z; a0.w += p0 * x0.w;
            a1.x += p1 * x1.x; a1.y += p1 * x1.y; a1.z += p1 * x1.z; a1.w += p1 * x1.w;
            a2.x += p2 * x2.x; a2.y += p2 * x2.y; a2.z += p2 * x2.z; a2.w += p2 * x2.w;
            a3.x += p3 * x3.x; a3.y += p3 * x3.y; a3.z += p3 * x3.z; a3.w += p3 * x3.w;
        }
        for (; j < cnt; j++) {
            float pj = __shfl_sync(0xffffffffu, pe, j);
            int   sj = __shfl_sync(0xffffffffu, sr, j);
            float4 xj = *(const float4*)(g_xl + (long long)sj * F + 4 * lane);
            a0.x += pj * xj.x; a0.y += pj * xj.y; a0.z += pj * xj.z; a0.w += pj * xj.w;
        }
    }
    float4 bi = *(const float4*)(bias + 4 * lane);
    float4 o;
    o.x = fmaxf((a0.x + a1.x + a2.x + a3.x) * inv + bi.x, 0.f);
    o.y = fmaxf((a0.y + a1.y + a2.y + a3.y) * inv + bi.y, 0.f);
    o.z = fmaxf((a0.z + a1.z + a2.z + a3.z) * inv + bi.z, 0.f);
    o.w = fmaxf((a0.w + a1.w + a2.w + a3.w) * inv + bi.w, 0.f);
    *(float4*)(hout + (long long)wid * F + 4 * lane) = o;
}

// ---------------- pool + classifier ----------------------------------------
__global__ void k_gptr(const void* __restrict__ batch) {
    int g = blockIdx.x * blockDim.x + threadIdx.x;
    if (g > NG) return;
    int lo = 0, hi = N_NODES;
    while (lo < hi) {
        int mid = (lo + hi) >> 1;
        if (getIdx(batch, mid) < g) lo = mid + 1; else hi = mid;
    }
    g_gptr[g] = lo;
}

__global__ void __launch_bounds__(128) k_poolg() {
    int g = blockIdx.x;
    int j = threadIdx.x;
    int b = g_gptr[g], e = g_gptr[g + 1];
    float acc = 0.f;
    for (int v = b; v < e; v++) acc += g_hA[(long long)v * F + j];
    float inv = 1.f / fmaxf((float)(e - b), 1.f);
    g_pool[g * F + j] = acc * inv;
}

__global__ void k_final(const float* __restrict__ lw, const float* __restrict__ lb,
                        float* __restrict__ out) {
    int t = blockIdx.x * blockDim.x + threadIdx.x;
    if (t >= NG * NC) return;
    int g = t / NC, cls = t % NC;
    float acc = lb[cls];
    #pragma unroll 8
    for (int c = 0; c < F; c++)
        acc += g_pool[g * F + c] * lw[c * NC + cls];
    out[t] = acc;
}

// ---------------- host -------------------------------------------------------
extern "C" void kernel_launch(void* const* d_in, const int* in_sizes, int n_in,
                              void* d_out, int out_size) {
    (void)in_sizes; (void)n_in; (void)out_size;
    const float* x     = (const float*)d_in[0];
    const void*  ei    = d_in[1];
    const void*  batch = d_in[2];
    // d_in[3] = dropout (identity in eval)
    const float* ea   = (const float*)d_in[4];
    const float* Wl   = (const float*)d_in[5];
    const float* bl   = (const float*)d_in[6];
    const float* Wr   = (const float*)d_in[7];
    const float* br   = (const float*)d_in[8];
    const float* We   = (const float*)d_in[9];
    const float* att  = (const float*)d_in[10];
    const float* bias = (const float*)d_in[11];
    const float* lw   = (const float*)d_in[12];
    const float* lb   = (const float*)d_in[13];
    float* out = (float*)d_out;

    k_probe_zero<<<(N_NODES + 255) / 256, 256>>>(ei);
    k_deg<<<(N_EDGESC + 255) / 256, 256>>>(ei);
    k_scanA<<<SCAN_NB, 1024>>>();
    k_scanB<<<1, 32>>>();
    k_scanC<<<(N_NODES + 255) / 256, 256>>>();
    k_scatter<<<(N_EDGESC + 255) / 256, 256>>>(ei);
    k_permute<<<2048, 256>>>(ea);
    k_loopcsr<<<(N_NODES * 32 + 255) / 256, 256>>>();

    int ntiles = (ET + 31) / 32;
    for (int l = 0; l < 3; l++) {
        int hin  = l;                 // 0: x, 1: hA, 2: hB
        int hout = (l == 1) ? 1 : 0;  // layer0 -> hA, layer1 -> hB, layer2 -> hA
        k_xlxr<<<(N_NODES + 31) / 32, 128>>>(x, hin,
                                             Wl + (size_t)l * F * F, bl + (size_t)l * F,
                                             Wr + (size_t)l * F * F, br + (size_t)l * F);
        k_score<<<(ntiles + SC_WARPS - 1) / SC_WARPS, 32 * SC_WARPS>>>(
            We + (size_t)l * FE * F, att + (size_t)l * F);
        k_agg<<<(N_NODES * 32 + 255) / 256, 256>>>(bias + (size_t)l * F, hout);
    }

    k_gptr<<<3, 256>>>(batch);
    k_poolg<<<NG, 128>>>();
    k_final<<<(NG * NC + 127) / 128, 128>>>(lw, lb, out);
}